// round 15
// baseline (speedup 1.0000x reference)
#include <cuda_runtime.h>

// Problem constants (fixed by the reference)
#define BB 4
#define SS 2048
#define DD 1024
#define HH 16
#define EE 64

// Scratch for Q/K/V in [b, h, s, e] layout (allocation-free rule: __device__ globals)
__device__ float g_Q[(size_t)BB * HH * SS * EE];
__device__ float g_K[(size_t)BB * HH * SS * EE];
__device__ float g_V[(size_t)BB * HH * SS * EE];

// ---------------------------------------------------------------------------
// Kernel 1: fused QKV projection.
// C[m, n] = sum_d x[m, d] * W[n, d],  m = b*S+s (8192), n = h*64+e (1024),
// grid.z in {0,1,2} selects (W_q -> g_Q), (W_k -> g_K), (W_v -> g_V).
// 64x64 block tile, BK=16, 128 threads, 8x4 register blocking.
// ---------------------------------------------------------------------------
__global__ __launch_bounds__(128)
void qkv_proj_kernel(const float* __restrict__ x,
                     const float* __restrict__ Wq,
                     const float* __restrict__ Wk,
                     const float* __restrict__ Wv)
{
    __shared__ __align__(16) float As[16][68];   // As[k][m], padded stride 68
    __shared__ __align__(16) float Bs[16][68];   // Bs[k][n]

    const int t  = threadIdx.x;
    const int tx = t & 15;     // 0..15 -> n direction (4 cols each)
    const int ty = t >> 4;     // 0..7  -> m direction (8 rows each)
    const int m0 = blockIdx.y * 64;
    const int n0 = blockIdx.x * 64;

    const float* W;
    float* outp;
    if (blockIdx.z == 0)      { W = Wq; outp = g_Q; }
    else if (blockIdx.z == 1) { W = Wk; outp = g_K; }
    else                      { W = Wv; outp = g_V; }

    // Global->shared load mapping: each thread owns one row of the 64-row tile
    // (lr = t/2) and 8 consecutive k-floats (lk = (t&1)*8) -> 2 float4 loads.
    const int lr = t >> 1;
    const int lk = (t & 1) * 8;
    const float* ag = x + (size_t)(m0 + lr) * DD + lk;
    const float* bg = W + (size_t)(n0 + lr) * DD + lk;

    float acc[8][4];
    #pragma unroll
    for (int i = 0; i < 8; i++)
        #pragma unroll
        for (int j = 0; j < 4; j++) acc[i][j] = 0.0f;

    for (int k0 = 0; k0 < DD; k0 += 16) {
        float4 a0 = *(const float4*)(ag + k0);
        float4 a1 = *(const float4*)(ag + k0 + 4);
        float4 b0 = *(const float4*)(bg + k0);
        float4 b1 = *(const float4*)(bg + k0 + 4);
        __syncthreads();   // previous iteration's readers are done
        As[lk + 0][lr] = a0.x; As[lk + 1][lr] = a0.y; As[lk + 2][lr] = a0.z; As[lk + 3][lr] = a0.w;
        As[lk + 4][lr] = a1.x; As[lk + 5][lr] = a1.y; As[lk + 6][lr] = a1.z; As[lk + 7][lr] = a1.w;
        Bs[lk + 0][lr] = b0.x; Bs[lk + 1][lr] = b0.y; Bs[lk + 2][lr] = b0.z; Bs[lk + 3][lr] = b0.w;
        Bs[lk + 4][lr] = b1.x; Bs[lk + 5][lr] = b1.y; Bs[lk + 6][lr] = b1.z; Bs[lk + 7][lr] = b1.w;
        __syncthreads();

        #pragma unroll
        for (int kk = 0; kk < 16; kk++) {
            float4 qa = *(const float4*)&As[kk][ty * 8];
            float4 qb = *(const float4*)&As[kk][ty * 8 + 4];
            float4 rb = *(const float4*)&Bs[kk][tx * 4];
            float ra[8] = {qa.x, qa.y, qa.z, qa.w, qb.x, qb.y, qb.z, qb.w};
            float rn[4] = {rb.x, rb.y, rb.z, rb.w};
            #pragma unroll
            for (int i = 0; i < 8; i++)
                #pragma unroll
                for (int j = 0; j < 4; j++)
                    acc[i][j] = fmaf(ra[i], rn[j], acc[i][j]);
        }
    }

    // Each 64-wide N tile is exactly one head (n0 multiple of 64).
    const int h = n0 >> 6;
    #pragma unroll
    for (int i = 0; i < 8; i++) {
        int m = m0 + ty * 8 + i;
        int b = m >> 11;          // m / 2048
        int s = m & (SS - 1);
        float4 v = make_float4(acc[i][0], acc[i][1], acc[i][2], acc[i][3]);
        *(float4*)&outp[(((size_t)b * HH + h) * SS + s) * EE + tx * 4] = v;
    }
}

// ---------------------------------------------------------------------------
// Kernel 2: flash attention per (b, h, 64-query tile).
// 128 threads; thread (tx, ty) owns S/P[q=8ty+i][k=4tx+j] and O[q=8ty+i][e=4tx+j].
// Online softmax over 32 KV tiles of 64.
// Dynamic smem: Qt[64][68] (e-major), Kt[64][68] (e-major), Ps[64][68], Vs[64][64].
// ---------------------------------------------------------------------------
#define ATTN_SMEM_FLOATS (3 * 64 * 68 + 64 * 64)
#define ATTN_SMEM_BYTES  (ATTN_SMEM_FLOATS * 4)   // 68608 B

__global__ __launch_bounds__(128)
void attn_kernel(float* __restrict__ out)
{
    extern __shared__ __align__(16) unsigned char smem_raw[];
    float* sm = (float*)smem_raw;
    float* Qt = sm;                 // Qt[e*68 + q]
    float* Kt = Qt + 64 * 68;       // Kt[e*68 + k]
    float* Ps = Kt + 64 * 68;       // Ps[q*68 + k]
    float* Vs = Ps + 64 * 68;       // Vs[k*64 + e]

    const int t  = threadIdx.x;
    const int tx = t & 15;
    const int ty = t >> 4;
    const int q0 = blockIdx.x * 64;
    const int h  = blockIdx.y;
    const int b  = blockIdx.z;

    const float* Qg = g_Q + (((size_t)b * HH + h) * SS + q0) * EE;
    const float* Kg = g_K + (((size_t)b * HH + h) * SS) * EE;
    const float* Vg = g_V + (((size_t)b * HH + h) * SS) * EE;

    // Load Q tile once, transposed to e-major (so S-GEMM reads are float4).
    #pragma unroll
    for (int r = 0; r < 8; r++) {
        int f = t + 128 * r;
        int q = f >> 4;
        int e = (f & 15) * 4;
        float4 v = *(const float4*)(Qg + q * EE + e);
        Qt[(e + 0) * 68 + q] = v.x;
        Qt[(e + 1) * 68 + q] = v.y;
        Qt[(e + 2) * 68 + q] = v.z;
        Qt[(e + 3) * 68 + q] = v.w;
    }

    float o[8][4];
    float mrow[8], lrow[8];
    #pragma unroll
    for (int i = 0; i < 8; i++) {
        mrow[i] = -1e30f;
        lrow[i] = 0.0f;
        #pragma unroll
        for (int j = 0; j < 4; j++) o[i][j] = 0.0f;
    }

    for (int kt = 0; kt < SS; kt += 64) {
        __syncthreads();   // previous tile fully consumed (also orders Q load on iter 0)

        // Load K tile (transposed to e-major) and V tile (natural k-major).
        #pragma unroll
        for (int r = 0; r < 8; r++) {
            int f = t + 128 * r;
            int k = f >> 4;
            int e = (f & 15) * 4;
            float4 kv = *(const float4*)(Kg + (size_t)(kt + k) * EE + e);
            Kt[(e + 0) * 68 + k] = kv.x;
            Kt[(e + 1) * 68 + k] = kv.y;
            Kt[(e + 2) * 68 + k] = kv.z;
            Kt[(e + 3) * 68 + k] = kv.w;
            float4 vv = *(const float4*)(Vg + (size_t)(kt + k) * EE + e);
            *(float4*)&Vs[k * 64 + e] = vv;
        }
        __syncthreads();

        // S = (Q K^T) * 1/sqrt(64)
        float sc[8][4];
        #pragma unroll
        for (int i = 0; i < 8; i++)
            #pragma unroll
            for (int j = 0; j < 4; j++) sc[i][j] = 0.0f;

        #pragma unroll 8
        for (int e = 0; e < 64; e++) {
            float4 qa = *(const float4*)&Qt[e * 68 + ty * 8];
            float4 qb = *(const float4*)&Qt[e * 68 + ty * 8 + 4];
            float4 kk = *(const float4*)&Kt[e * 68 + tx * 4];
            float ra[8] = {qa.x, qa.y, qa.z, qa.w, qb.x, qb.y, qb.z, qb.w};
            float rk[4] = {kk.x, kk.y, kk.z, kk.w};
            #pragma unroll
            for (int i = 0; i < 8; i++)
                #pragma unroll
                for (int j = 0; j < 4; j++)
                    sc[i][j] = fmaf(ra[i], rk[j], sc[i][j]);
        }
        #pragma unroll
        for (int i = 0; i < 8; i++)
            #pragma unroll
            for (int j = 0; j < 4; j++) sc[i][j] *= 0.125f;

        // Online softmax update per q row. Row spreads over 16 tx lanes (same ty
        // half-warp): xor-shuffle over lane bits 0..3 reduces exactly over tx.
        #pragma unroll
        for (int i = 0; i < 8; i++) {
            float rm = fmaxf(fmaxf(sc[i][0], sc[i][1]), fmaxf(sc[i][2], sc[i][3]));
            rm = fmaxf(rm, __shfl_xor_sync(0xffffffffu, rm, 1));
            rm = fmaxf(rm, __shfl_xor_sync(0xffffffffu, rm, 2));
            rm = fmaxf(rm, __shfl_xor_sync(0xffffffffu, rm, 4));
            rm = fmaxf(rm, __shfl_xor_sync(0xffffffffu, rm, 8));
            float mnew = fmaxf(mrow[i], rm);
            float corr = __expf(mrow[i] - mnew);
            mrow[i] = mnew;
            float rs = 0.0f;
            #pragma unroll
            for (int j = 0; j < 4; j++) {
                float p = __expf(sc[i][j] - mnew);
                sc[i][j] = p;
                rs += p;
            }
            rs += __shfl_xor_sync(0xffffffffu, rs, 1);
            rs += __shfl_xor_sync(0xffffffffu, rs, 2);
            rs += __shfl_xor_sync(0xffffffffu, rs, 4);
            rs += __shfl_xor_sync(0xffffffffu, rs, 8);
            lrow[i] = lrow[i] * corr + rs;
            #pragma unroll
            for (int j = 0; j < 4; j++) o[i][j] *= corr;
            *(float4*)&Ps[(ty * 8 + i) * 68 + tx * 4] =
                make_float4(sc[i][0], sc[i][1], sc[i][2], sc[i][3]);
        }
        __syncthreads();

        // O += P V   (Ps reads are 2-address broadcasts; Vs reads are float4)
        #pragma unroll 8
        for (int k = 0; k < 64; k++) {
            float rp[8];
            #pragma unroll
            for (int i = 0; i < 8; i++) rp[i] = Ps[(ty * 8 + i) * 68 + k];
            float4 vv = *(const float4*)&Vs[k * 64 + tx * 4];
            #pragma unroll
            for (int i = 0; i < 8; i++) {
                o[i][0] = fmaf(rp[i], vv.x, o[i][0]);
                o[i][1] = fmaf(rp[i], vv.y, o[i][1]);
                o[i][2] = fmaf(rp[i], vv.z, o[i][2]);
                o[i][3] = fmaf(rp[i], vv.w, o[i][3]);
            }
        }
    }

    // Epilogue: out[b, s, h*64 + e] = O / l
    #pragma unroll
    for (int i = 0; i < 8; i++) {
        float inv = 1.0f / lrow[i];
        int q = q0 + ty * 8 + i;
        float4 r = make_float4(o[i][0] * inv, o[i][1] * inv, o[i][2] * inv, o[i][3] * inv);
        *(float4*)&out[((size_t)b * SS + q) * (HH * EE) + h * EE + tx * 4] = r;
    }
}

// ---------------------------------------------------------------------------
// Launch: projection (16 x 128 x 3 blocks), then attention (32 x 16 x 4 blocks).
// Default-stream launches only; graph-capturable; no allocations.
// ---------------------------------------------------------------------------
extern "C" void kernel_launch(void* const* d_in, const int* in_sizes, int n_in,
                              void* d_out, int out_size)
{
    (void)in_sizes; (void)n_in; (void)out_size;
    const float* x  = (const float*)d_in[0];
    const float* Wq = (const float*)d_in[1];
    const float* Wk = (const float*)d_in[2];
    const float* Wv = (const float*)d_in[3];
    float* out = (float*)d_out;

    // Opt in to >48KB dynamic smem for the attention kernel (idempotent,
    // not a stream op, safe under graph capture).
    cudaFuncSetAttribute(attn_kernel,
                         cudaFuncAttributeMaxDynamicSharedMemorySize,
                         ATTN_SMEM_BYTES);

    dim3 gproj(HH * EE / 64, (BB * SS) / 64, 3);   // (16, 128, 3)
    qkv_proj_kernel<<<gproj, 128>>>(x, Wq, Wk, Wv);

    dim3 gattn(SS / 64, HH, BB);                   // (32, 16, 4)
    attn_kernel<<<gattn, 128, ATTN_SMEM_BYTES>>>(out);
}

// round 16
// speedup vs baseline: 1.8928x; 1.8928x over previous
#include <cuda_runtime.h>

// Problem constants
#define BB 4
#define SS 2048
#define DD 1024
#define HH 16
#define EE 64

// Q/K/V scratch in [b, h, s, e] (allocation-free rule: __device__ globals)
__device__ float g_Q[(size_t)BB * HH * SS * EE];
__device__ float g_K[(size_t)BB * HH * SS * EE];
__device__ float g_V[(size_t)BB * HH * SS * EE];

// ---------------------------------------------------------------------------
// tf32 helpers
// ---------------------------------------------------------------------------
__device__ __forceinline__ unsigned f2tf(float f) {
    unsigned u;
    asm("cvt.rna.tf32.f32 %0, %1;" : "=r"(u) : "f"(f));
    return u;
}

// D += A(16x8, row) * B(8x8, col), tf32 inputs, f32 accum.
__device__ __forceinline__ void mma8(float* c, const unsigned* a, const unsigned* b) {
    asm("mma.sync.aligned.m16n8k8.row.col.f32.tf32.tf32.f32 "
        "{%0,%1,%2,%3}, {%4,%5,%6,%7}, {%8,%9}, {%0,%1,%2,%3};"
        : "+f"(c[0]), "+f"(c[1]), "+f"(c[2]), "+f"(c[3])
        : "r"(a[0]), "r"(a[1]), "r"(a[2]), "r"(a[3]), "r"(b[0]), "r"(b[1]));
}

// Fragment layouts (m16n8k8):
//   A: a0 (r=lane>>2, c=lane&3), a1 (r+8, c), a2 (r, c+4), a3 (r+8, c+4)
//   B: b0 (k=lane&3, n=lane>>2), b1 (k+4, n)
//   C: c0 (r=lane>>2, n=2*(lane&3)), c1 (r, n+1), c2 (r+8, n), c3 (r+8, n+1)

// ---------------------------------------------------------------------------
// Kernel 1: QKV projection, C[m,n] = sum_d x[m,d] * W[n,d].
// Block tile 128(m) x 128(n) x 16(k), 256 threads = 8 warps (2m x 4n),
// warp tile 64x32. Double-buffered smem in fragment-major tf32 layout.
// grid.z selects Wq->g_Q / Wk->g_K / Wv->g_V.
// ---------------------------------------------------------------------------
__global__ __launch_bounds__(256, 1)
void qkv_proj_mma(const float* __restrict__ x,
                  const float* __restrict__ Wq,
                  const float* __restrict__ Wk,
                  const float* __restrict__ Wv)
{
    // Fragment-major: A [kstep(2)][mtile(8)][lane(32)][4], B [kstep(2)][ntile(16)][lane(32)][2]
    __shared__ unsigned Asm[2][2048];
    __shared__ unsigned Bsm[2][2048];

    const int t    = threadIdx.x;
    const int lane = t & 31;
    const int warp = t >> 5;
    const int wm   = warp >> 2;   // 0..1 -> 64 rows
    const int wn   = warp & 3;    // 0..3 -> 32 cols
    const int m0   = blockIdx.y * 128;
    const int n0   = blockIdx.x * 128;

    const float* W;
    float* outp;
    if (blockIdx.z == 0)      { W = Wq; outp = g_Q; }
    else if (blockIdx.z == 1) { W = Wk; outp = g_K; }
    else                      { W = Wv; outp = g_V; }

    // Loader: thread t owns row lr = t>>1, 8 cols starting at (t&1)*8.
    const int lr   = t >> 1;
    const int ks_l = t & 1;
    const float* ag = x + (size_t)(m0 + lr) * DD + ks_l * 8;
    const float* bg = W + (size_t)(n0 + lr) * DD + ks_l * 8;

    // Fragment scatter bases for this thread's 8 elements (cc = 0..7 within kstep)
    const int rr = lr & 15;
    const unsigned offA0 = ((unsigned)(ks_l * 8  + (lr >> 4)) * 32 + (rr & 7) * 4) * 4 + (rr >> 3);
    const unsigned offB0 = ((unsigned)(ks_l * 16 + (lr >> 3)) * 32 + (lr & 7) * 4) * 2;

    float acc[4][4][4];
    #pragma unroll
    for (int i = 0; i < 4; i++)
        #pragma unroll
        for (int j = 0; j < 4; j++)
            #pragma unroll
            for (int v = 0; v < 4; v++) acc[i][j][v] = 0.0f;

    float4 av0 = *(const float4*)(ag);
    float4 av1 = *(const float4*)(ag + 4);
    float4 bv0 = *(const float4*)(bg);
    float4 bv1 = *(const float4*)(bg + 4);

    // scatter stage 0
    {
        float va[8] = {av0.x, av0.y, av0.z, av0.w, av1.x, av1.y, av1.z, av1.w};
        float vb[8] = {bv0.x, bv0.y, bv0.z, bv0.w, bv1.x, bv1.y, bv1.z, bv1.w};
        #pragma unroll
        for (int cc = 0; cc < 8; cc++) {
            Asm[0][offA0 + (cc & 3) * 4 + (cc >> 2) * 2] = f2tf(va[cc]);
            Bsm[0][offB0 + (cc & 3) * 2 + (cc >> 2)]     = f2tf(vb[cc]);
        }
    }
    __syncthreads();

    for (int kt = 0; kt < DD / 16; kt++) {
        const int cur = kt & 1;
        if (kt < DD / 16 - 1) {
            const float* ap = ag + (kt + 1) * 16;
            const float* bp = bg + (kt + 1) * 16;
            av0 = *(const float4*)(ap);
            av1 = *(const float4*)(ap + 4);
            bv0 = *(const float4*)(bp);
            bv1 = *(const float4*)(bp + 4);
        }

        #pragma unroll
        for (int ks = 0; ks < 2; ks++) {
            unsigned a[4][4], b[4][2];
            #pragma unroll
            for (int i = 0; i < 4; i++) {
                uint4 q = *(const uint4*)&Asm[cur][((ks * 8 + wm * 4 + i) * 32 + lane) * 4];
                a[i][0] = q.x; a[i][1] = q.y; a[i][2] = q.z; a[i][3] = q.w;
            }
            #pragma unroll
            for (int j = 0; j < 4; j++) {
                uint2 q = *(const uint2*)&Bsm[cur][((ks * 16 + wn * 4 + j) * 32 + lane) * 2];
                b[j][0] = q.x; b[j][1] = q.y;
            }
            #pragma unroll
            for (int i = 0; i < 4; i++)
                #pragma unroll
                for (int j = 0; j < 4; j++)
                    mma8(acc[i][j], a[i], b[j]);
        }

        if (kt < DD / 16 - 1) {
            float va[8] = {av0.x, av0.y, av0.z, av0.w, av1.x, av1.y, av1.z, av1.w};
            float vb[8] = {bv0.x, bv0.y, bv0.z, bv0.w, bv1.x, bv1.y, bv1.z, bv1.w};
            #pragma unroll
            for (int cc = 0; cc < 8; cc++) {
                Asm[cur ^ 1][offA0 + (cc & 3) * 4 + (cc >> 2) * 2] = f2tf(va[cc]);
                Bsm[cur ^ 1][offB0 + (cc & 3) * 2 + (cc >> 2)]     = f2tf(vb[cc]);
            }
        }
        __syncthreads();
    }

    // Epilogue: write into [b, h, s, e] (head boundaries at n%64; pairs stay in-head)
    #pragma unroll
    for (int i = 0; i < 4; i++) {
        int r = m0 + wm * 64 + i * 16 + (lane >> 2);
        #pragma unroll
        for (int j = 0; j < 4; j++) {
            int n = n0 + wn * 32 + j * 8 + 2 * (lane & 3);
            int h = n >> 6, e = n & 63;
            int bq = r >> 11, s = r & (SS - 1);
            size_t base = (((size_t)bq * HH + h) * SS);
            *(float2*)&outp[(base + s) * EE + e]     = make_float2(acc[i][j][0], acc[i][j][1]);
            *(float2*)&outp[(base + s + 8) * EE + e] = make_float2(acc[i][j][2], acc[i][j][3]);
        }
    }
}

// ---------------------------------------------------------------------------
// Kernel 2: flash attention, tf32 mma. One block per (b, h, 128-query tile).
// 256 threads = 8 warps, warp grid 4(m=32q) x 2(n=32 keys / 32 e-cols).
// Q lives in registers as tf32 A-fragments (pre-scaled by 1/8).
// KV tiles of 64 keys; K/V staged to fragment-major tf32 smem; P staged to
// row-major tf32 smem (ld=68: conflict-free A-frag reads).
// ---------------------------------------------------------------------------
#define PLD 68
#define ATTN_SMEM_U32 (4096 + 4096 + 128 * PLD + 256 + 256)
#define ATTN_SMEM_BYTES (ATTN_SMEM_U32 * 4)

__global__ __launch_bounds__(256, 1)
void attn_mma(float* __restrict__ out)
{
    extern __shared__ unsigned smem_u[];
    unsigned* Kf   = smem_u;                     // [kstep(8)][ntile(8)][lane][2]
    unsigned* Vf   = Kf + 4096;                  // [kstep(8)][ntile(8)][lane][2]
    unsigned* Psm  = Vf + 4096;                  // [128][PLD] tf32 bits
    float*    pmax = (float*)(Psm + 128 * PLD);  // [2][128]
    float*    psum = pmax + 256;                 // [2][128]

    const int t    = threadIdx.x;
    const int lane = t & 31;
    const int warp = t >> 5;
    const int wm   = warp >> 1;   // 0..3 -> 32 q-rows
    const int wn   = warp & 1;    // 0..1 -> 32 keys (S) / 32 e-cols (PV)
    const int q0   = blockIdx.x * 128;
    const int h    = blockIdx.y;
    const int b    = blockIdx.z;

    const float* Qg = g_Q + (((size_t)b * HH + h) * SS + q0) * EE;
    const float* Kg = g_K + ((size_t)b * HH + h) * SS * EE;
    const float* Vg = g_V + ((size_t)b * HH + h) * SS * EE;

    // Q A-fragments in registers, pre-scaled by 1/sqrt(64)
    unsigned qf[2][8][4];
    #pragma unroll
    for (int mt = 0; mt < 2; mt++) {
        int r0 = wm * 32 + mt * 16 + (lane >> 2);
        #pragma unroll
        for (int ks = 0; ks < 8; ks++) {
            int c0 = ks * 8 + (lane & 3);
            qf[mt][ks][0] = f2tf(Qg[(size_t)r0 * EE + c0] * 0.125f);
            qf[mt][ks][1] = f2tf(Qg[(size_t)(r0 + 8) * EE + c0] * 0.125f);
            qf[mt][ks][2] = f2tf(Qg[(size_t)r0 * EE + c0 + 4] * 0.125f);
            qf[mt][ks][3] = f2tf(Qg[(size_t)(r0 + 8) * EE + c0 + 4] * 0.125f);
        }
    }

    float o[2][4][4];
    float mrow[2][2], lrow[2][2];
    #pragma unroll
    for (int mt = 0; mt < 2; mt++) {
        mrow[mt][0] = mrow[mt][1] = -1e30f;
        lrow[mt][0] = lrow[mt][1] = 0.0f;
        #pragma unroll
        for (int j = 0; j < 4; j++)
            #pragma unroll
            for (int v = 0; v < 4; v++) o[mt][j][v] = 0.0f;
    }

    // KV prefetch: thread t owns key row pr = t>>2, 16 e-cols at pc.
    const int pr = t >> 2;
    const int pc = (t & 3) * 16;
    float4 kv[4], vv[4];
    #pragma unroll
    for (int u = 0; u < 4; u++) {
        kv[u] = *(const float4*)(Kg + (size_t)pr * EE + pc + u * 4);
        vv[u] = *(const float4*)(Vg + (size_t)pr * EE + pc + u * 4);
    }

    for (int kt = 0; kt < SS; kt += 64) {
        __syncthreads();   // Kf/Vf/Psm free (prior PV done)

        // Scatter K (B-frag over n=key, k=e) and V (B-frag over n=e, k=key)
        #pragma unroll
        for (int u = 0; u < 4; u++) {
            const float* kp = (const float*)&kv[u];
            const float* vp = (const float*)&vv[u];
            #pragma unroll
            for (int w = 0; w < 4; w++) {
                int e = pc + u * 4 + w;
                Kf[(((e >> 3) * 8 + (pr >> 3)) * 32 + (pr & 7) * 4 + (e & 3)) * 2 + ((e >> 2) & 1)] = f2tf(kp[w]);
                Vf[(((pr >> 3) * 8 + (e >> 3)) * 32 + (e & 7) * 4 + (pr & 3)) * 2 + ((pr >> 2) & 1)] = f2tf(vp[w]);
            }
        }
        __syncthreads();

        if (kt + 64 < SS) {
            #pragma unroll
            for (int u = 0; u < 4; u++) {
                kv[u] = *(const float4*)(Kg + (size_t)(kt + 64 + pr) * EE + pc + u * 4);
                vv[u] = *(const float4*)(Vg + (size_t)(kt + 64 + pr) * EE + pc + u * 4);
            }
        }

        // S = Q K^T (scaled): sc[mt][j][4], warp covers 32q x 32keys
        float sc[2][4][4];
        #pragma unroll
        for (int mt = 0; mt < 2; mt++)
            #pragma unroll
            for (int j = 0; j < 4; j++)
                #pragma unroll
                for (int v = 0; v < 4; v++) sc[mt][j][v] = 0.0f;

        #pragma unroll
        for (int ks = 0; ks < 8; ks++) {
            unsigned bf[4][2];
            #pragma unroll
            for (int j = 0; j < 4; j++) {
                uint2 q = *(const uint2*)&Kf[((ks * 8 + wn * 4 + j) * 32 + lane) * 2];
                bf[j][0] = q.x; bf[j][1] = q.y;
            }
            #pragma unroll
            for (int mt = 0; mt < 2; mt++)
                #pragma unroll
                for (int j = 0; j < 4; j++)
                    mma8(sc[mt][j], qf[mt][ks], bf[j]);
        }

        // Partial row max over this warp's 32 keys (in-lane over j, shuffle over lane&3)
        float pm[2][2];
        #pragma unroll
        for (int mt = 0; mt < 2; mt++) {
            float m0v = fmaxf(sc[mt][0][0], sc[mt][0][1]);
            float m1v = fmaxf(sc[mt][0][2], sc[mt][0][3]);
            #pragma unroll
            for (int j = 1; j < 4; j++) {
                m0v = fmaxf(m0v, fmaxf(sc[mt][j][0], sc[mt][j][1]));
                m1v = fmaxf(m1v, fmaxf(sc[mt][j][2], sc[mt][j][3]));
            }
            m0v = fmaxf(m0v, __shfl_xor_sync(0xffffffffu, m0v, 1));
            m0v = fmaxf(m0v, __shfl_xor_sync(0xffffffffu, m0v, 2));
            m1v = fmaxf(m1v, __shfl_xor_sync(0xffffffffu, m1v, 1));
            m1v = fmaxf(m1v, __shfl_xor_sync(0xffffffffu, m1v, 2));
            pm[mt][0] = m0v; pm[mt][1] = m1v;
        }
        if ((lane & 3) == 0) {
            #pragma unroll
            for (int mt = 0; mt < 2; mt++) {
                int rbase = wm * 32 + mt * 16 + (lane >> 2);
                pmax[wn * 128 + rbase]     = pm[mt][0];
                pmax[wn * 128 + rbase + 8] = pm[mt][1];
            }
        }
        __syncthreads();

        // Combine across the two n-warps; update m, rescale l and O
        float mnew[2][2], corr[2][2];
        #pragma unroll
        for (int mt = 0; mt < 2; mt++) {
            int rbase = wm * 32 + mt * 16 + (lane >> 2);
            #pragma unroll
            for (int hf = 0; hf < 2; hf++) {
                float om = pmax[(wn ^ 1) * 128 + rbase + hf * 8];
                float mn = fmaxf(mrow[mt][hf], fmaxf(pm[mt][hf], om));
                corr[mt][hf] = __expf(mrow[mt][hf] - mn);
                mrow[mt][hf] = mn;
                lrow[mt][hf] *= corr[mt][hf];
                mnew[mt][hf] = mn;
            }
        }
        #pragma unroll
        for (int mt = 0; mt < 2; mt++)
            #pragma unroll
            for (int j = 0; j < 4; j++) {
                o[mt][j][0] *= corr[mt][0];
                o[mt][j][1] *= corr[mt][0];
                o[mt][j][2] *= corr[mt][1];
                o[mt][j][3] *= corr[mt][1];
            }

        // exp, partial sums, write P (tf32 bits) to Psm
        float ps[2][2] = {{0.0f, 0.0f}, {0.0f, 0.0f}};
        #pragma unroll
        for (int mt = 0; mt < 2; mt++) {
            int r = wm * 32 + mt * 16 + (lane >> 2);
            #pragma unroll
            for (int j = 0; j < 4; j++) {
                int c = wn * 32 + j * 8 + 2 * (lane & 3);
                float p0 = __expf(sc[mt][j][0] - mnew[mt][0]);
                float p1 = __expf(sc[mt][j][1] - mnew[mt][0]);
                float p2 = __expf(sc[mt][j][2] - mnew[mt][1]);
                float p3 = __expf(sc[mt][j][3] - mnew[mt][1]);
                ps[mt][0] += p0 + p1;
                ps[mt][1] += p2 + p3;
                *(uint2*)&Psm[r * PLD + c]       = make_uint2(f2tf(p0), f2tf(p1));
                *(uint2*)&Psm[(r + 8) * PLD + c] = make_uint2(f2tf(p2), f2tf(p3));
            }
        }
        #pragma unroll
        for (int mt = 0; mt < 2; mt++)
            #pragma unroll
            for (int hf = 0; hf < 2; hf++) {
                float s = ps[mt][hf];
                s += __shfl_xor_sync(0xffffffffu, s, 1);
                s += __shfl_xor_sync(0xffffffffu, s, 2);
                ps[mt][hf] = s;
            }
        if ((lane & 3) == 0) {
            #pragma unroll
            for (int mt = 0; mt < 2; mt++) {
                int rbase = wm * 32 + mt * 16 + (lane >> 2);
                psum[wn * 128 + rbase]     = ps[mt][0];
                psum[wn * 128 + rbase + 8] = ps[mt][1];
            }
        }
        __syncthreads();

        #pragma unroll
        for (int mt = 0; mt < 2; mt++) {
            int rbase = wm * 32 + mt * 16 + (lane >> 2);
            lrow[mt][0] += ps[mt][0] + psum[(wn ^ 1) * 128 + rbase];
            lrow[mt][1] += ps[mt][1] + psum[(wn ^ 1) * 128 + rbase + 8];
        }

        // O += P V : A = P rows (own 32q x 64keys), B = V frags (e-range wn*32)
        #pragma unroll
        for (int ks = 0; ks < 8; ks++) {
            unsigned pa[2][4];
            #pragma unroll
            for (int mt = 0; mt < 2; mt++) {
                int r = wm * 32 + mt * 16 + (lane >> 2);
                int c = ks * 8 + (lane & 3);
                pa[mt][0] = Psm[r * PLD + c];
                pa[mt][1] = Psm[(r + 8) * PLD + c];
                pa[mt][2] = Psm[r * PLD + c + 4];
                pa[mt][3] = Psm[(r + 8) * PLD + c + 4];
            }
            unsigned vb[4][2];
            #pragma unroll
            for (int j = 0; j < 4; j++) {
                uint2 q = *(const uint2*)&Vf[((ks * 8 + wn * 4 + j) * 32 + lane) * 2];
                vb[j][0] = q.x; vb[j][1] = q.y;
            }
            #pragma unroll
            for (int mt = 0; mt < 2; mt++)
                #pragma unroll
                for (int j = 0; j < 4; j++)
                    mma8(o[mt][j], pa[mt], vb[j]);
        }
    }

    // Epilogue: out[b, q, h*64 + e] = O / l
    #pragma unroll
    for (int mt = 0; mt < 2; mt++) {
        float i0 = 1.0f / lrow[mt][0];
        float i1 = 1.0f / lrow[mt][1];
        int r = q0 + wm * 32 + mt * 16 + (lane >> 2);
        #pragma unroll
        for (int j = 0; j < 4; j++) {
            int e = h * EE + wn * 32 + j * 8 + 2 * (lane & 3);
            *(float2*)&out[((size_t)b * SS + r) * (HH * EE) + e] =
                make_float2(o[mt][j][0] * i0, o[mt][j][1] * i0);
            *(float2*)&out[((size_t)b * SS + r + 8) * (HH * EE) + e] =
                make_float2(o[mt][j][2] * i1, o[mt][j][3] * i1);
        }
    }
}

// ---------------------------------------------------------------------------
// Launch
// ---------------------------------------------------------------------------
extern "C" void kernel_launch(void* const* d_in, const int* in_sizes, int n_in,
                              void* d_out, int out_size)
{
    (void)in_sizes; (void)n_in; (void)out_size;
    const float* x  = (const float*)d_in[0];
    const float* Wq = (const float*)d_in[1];
    const float* Wk = (const float*)d_in[2];
    const float* Wv = (const float*)d_in[3];
    float* out = (float*)d_out;

    cudaFuncSetAttribute(attn_mma,
                         cudaFuncAttributeMaxDynamicSharedMemorySize,
                         ATTN_SMEM_BYTES);

    dim3 gproj(HH * EE / 128, (BB * SS) / 128, 3);   // (8, 64, 3)
    qkv_proj_mma<<<gproj, 256>>>(x, Wq, Wk, Wv);

    dim3 gattn(SS / 128, HH, BB);                     // (16, 16, 4)
    attn_mma<<<gattn, 256, ATTN_SMEM_BYTES>>>(out);
}

// round 17
// speedup vs baseline: 1.8950x; 1.0012x over previous
#include <cuda_runtime.h>

// Problem constants
#define BB 4
#define SS 2048
#define DD 1024
#define HH 16
#define EE 64

// Q/K/V scratch in [b, h, s, e] (allocation-free rule: __device__ globals)
__device__ float g_Q[(size_t)BB * HH * SS * EE];
__device__ float g_K[(size_t)BB * HH * SS * EE];
__device__ float g_V[(size_t)BB * HH * SS * EE];

// ---------------------------------------------------------------------------
// tf32 helpers
// ---------------------------------------------------------------------------
__device__ __forceinline__ unsigned f2tf(float f) {
    unsigned u;
    asm("cvt.rna.tf32.f32 %0, %1;" : "=r"(u) : "f"(f));
    return u;
}

// D += A(16x8, row) * B(8x8, col), tf32 inputs, f32 accum.
__device__ __forceinline__ void mma8(float* c, const unsigned* a, const unsigned* b) {
    asm("mma.sync.aligned.m16n8k8.row.col.f32.tf32.tf32.f32 "
        "{%0,%1,%2,%3}, {%4,%5,%6,%7}, {%8,%9}, {%0,%1,%2,%3};"
        : "+f"(c[0]), "+f"(c[1]), "+f"(c[2]), "+f"(c[3])
        : "r"(a[0]), "r"(a[1]), "r"(a[2]), "r"(a[3]), "r"(b[0]), "r"(b[1]));
}

// Fragment layouts (m16n8k8):
//   A: a0 (r=lane>>2, c=lane&3), a1 (r+8, c), a2 (r, c+4), a3 (r+8, c+4)
//   B: b0 (k=lane&3, n=lane>>2), b1 (k+4, n)
//   C: c0 (r=lane>>2, n=2*(lane&3)), c1 (r, n+1), c2 (r+8, n), c3 (r+8, n+1)

// ---------------------------------------------------------------------------
// Kernel 1: QKV projection, C[m,n] = sum_d x[m,d] * W[n,d].
// Block tile 128(m) x 128(n) x 16(k), 256 threads = 8 warps (2m x 4n),
// warp tile 64x32. Double-buffered smem in fragment-major tf32 layout.
// grid.z selects Wq->g_Q / Wk->g_K / Wv->g_V.
// ---------------------------------------------------------------------------
__global__ __launch_bounds__(256, 1)
void qkv_proj_mma(const float* __restrict__ x,
                  const float* __restrict__ Wq,
                  const float* __restrict__ Wk,
                  const float* __restrict__ Wv)
{
    // Fragment-major: A [kstep(2)][mtile(8)][lane(32)][4], B [kstep(2)][ntile(16)][lane(32)][2]
    __shared__ unsigned Asm[2][2048];
    __shared__ unsigned Bsm[2][2048];

    const int t    = threadIdx.x;
    const int lane = t & 31;
    const int warp = t >> 5;
    const int wm   = warp >> 2;   // 0..1 -> 64 rows
    const int wn   = warp & 3;    // 0..3 -> 32 cols
    const int m0   = blockIdx.y * 128;
    const int n0   = blockIdx.x * 128;

    const float* W;
    float* outp;
    if (blockIdx.z == 0)      { W = Wq; outp = g_Q; }
    else if (blockIdx.z == 1) { W = Wk; outp = g_K; }
    else                      { W = Wv; outp = g_V; }

    // Loader: thread t owns row lr = t>>1, 8 cols starting at (t&1)*8.
    const int lr   = t >> 1;
    const int ks_l = t & 1;
    const float* ag = x + (size_t)(m0 + lr) * DD + ks_l * 8;
    const float* bg = W + (size_t)(n0 + lr) * DD + ks_l * 8;

    // Fragment scatter bases for this thread's 8 elements (cc = 0..7 within kstep)
    const int rr = lr & 15;
    const unsigned offA0 = ((unsigned)(ks_l * 8  + (lr >> 4)) * 32 + (rr & 7) * 4) * 4 + (rr >> 3);
    const unsigned offB0 = ((unsigned)(ks_l * 16 + (lr >> 3)) * 32 + (lr & 7) * 4) * 2;

    float acc[4][4][4];
    #pragma unroll
    for (int i = 0; i < 4; i++)
        #pragma unroll
        for (int j = 0; j < 4; j++)
            #pragma unroll
            for (int v = 0; v < 4; v++) acc[i][j][v] = 0.0f;

    float4 av0 = *(const float4*)(ag);
    float4 av1 = *(const float4*)(ag + 4);
    float4 bv0 = *(const float4*)(bg);
    float4 bv1 = *(const float4*)(bg + 4);

    // scatter stage 0
    {
        float va[8] = {av0.x, av0.y, av0.z, av0.w, av1.x, av1.y, av1.z, av1.w};
        float vb[8] = {bv0.x, bv0.y, bv0.z, bv0.w, bv1.x, bv1.y, bv1.z, bv1.w};
        #pragma unroll
        for (int cc = 0; cc < 8; cc++) {
            Asm[0][offA0 + (cc & 3) * 4 + (cc >> 2) * 2] = f2tf(va[cc]);
            Bsm[0][offB0 + (cc & 3) * 2 + (cc >> 2)]     = f2tf(vb[cc]);
        }
    }
    __syncthreads();

    for (int kt = 0; kt < DD / 16; kt++) {
        const int cur = kt & 1;
        if (kt < DD / 16 - 1) {
            const float* ap = ag + (kt + 1) * 16;
            const float* bp = bg + (kt + 1) * 16;
            av0 = *(const float4*)(ap);
            av1 = *(const float4*)(ap + 4);
            bv0 = *(const float4*)(bp);
            bv1 = *(const float4*)(bp + 4);
        }

        #pragma unroll
        for (int ks = 0; ks < 2; ks++) {
            unsigned a[4][4], b[4][2];
            #pragma unroll
            for (int i = 0; i < 4; i++) {
                uint4 q = *(const uint4*)&Asm[cur][((ks * 8 + wm * 4 + i) * 32 + lane) * 4];
                a[i][0] = q.x; a[i][1] = q.y; a[i][2] = q.z; a[i][3] = q.w;
            }
            #pragma unroll
            for (int j = 0; j < 4; j++) {
                uint2 q = *(const uint2*)&Bsm[cur][((ks * 16 + wn * 4 + j) * 32 + lane) * 2];
                b[j][0] = q.x; b[j][1] = q.y;
            }
            #pragma unroll
            for (int i = 0; i < 4; i++)
                #pragma unroll
                for (int j = 0; j < 4; j++)
                    mma8(acc[i][j], a[i], b[j]);
        }

        if (kt < DD / 16 - 1) {
            float va[8] = {av0.x, av0.y, av0.z, av0.w, av1.x, av1.y, av1.z, av1.w};
            float vb[8] = {bv0.x, bv0.y, bv0.z, bv0.w, bv1.x, bv1.y, bv1.z, bv1.w};
            #pragma unroll
            for (int cc = 0; cc < 8; cc++) {
                Asm[cur ^ 1][offA0 + (cc & 3) * 4 + (cc >> 2) * 2] = f2tf(va[cc]);
                Bsm[cur ^ 1][offB0 + (cc & 3) * 2 + (cc >> 2)]     = f2tf(vb[cc]);
            }
        }
        __syncthreads();
    }

    // Epilogue: write into [b, h, s, e] (head boundaries at n%64; pairs stay in-head)
    #pragma unroll
    for (int i = 0; i < 4; i++) {
        int r = m0 + wm * 64 + i * 16 + (lane >> 2);
        #pragma unroll
        for (int j = 0; j < 4; j++) {
            int n = n0 + wn * 32 + j * 8 + 2 * (lane & 3);
            int h = n >> 6, e = n & 63;
            int bq = r >> 11, s = r & (SS - 1);
            size_t base = (((size_t)bq * HH + h) * SS);
            *(float2*)&outp[(base + s) * EE + e]     = make_float2(acc[i][j][0], acc[i][j][1]);
            *(float2*)&outp[(base + s + 8) * EE + e] = make_float2(acc[i][j][2], acc[i][j][3]);
        }
    }
}

// ---------------------------------------------------------------------------
// Kernel 2: flash attention, tf32 mma. One block per (b, h, 128-query tile).
// 256 threads = 8 warps, warp grid 4(m=32q) x 2(n=32 keys / 32 e-cols).
// Q lives in registers as tf32 A-fragments (pre-scaled by 1/8).
// KV tiles of 64 keys; K/V staged to fragment-major tf32 smem; P staged to
// row-major tf32 smem (ld=68: conflict-free A-frag reads).
// ---------------------------------------------------------------------------
#define PLD 68
#define ATTN_SMEM_U32 (4096 + 4096 + 128 * PLD + 256 + 256)
#define ATTN_SMEM_BYTES (ATTN_SMEM_U32 * 4)

__global__ __launch_bounds__(256, 1)
void attn_mma(float* __restrict__ out)
{
    extern __shared__ unsigned smem_u[];
    unsigned* Kf   = smem_u;                     // [kstep(8)][ntile(8)][lane][2]
    unsigned* Vf   = Kf + 4096;                  // [kstep(8)][ntile(8)][lane][2]
    unsigned* Psm  = Vf + 4096;                  // [128][PLD] tf32 bits
    float*    pmax = (float*)(Psm + 128 * PLD);  // [2][128]
    float*    psum = pmax + 256;                 // [2][128]

    const int t    = threadIdx.x;
    const int lane = t & 31;
    const int warp = t >> 5;
    const int wm   = warp >> 1;   // 0..3 -> 32 q-rows
    const int wn   = warp & 1;    // 0..1 -> 32 keys (S) / 32 e-cols (PV)
    const int q0   = blockIdx.x * 128;
    const int h    = blockIdx.y;
    const int b    = blockIdx.z;

    const float* Qg = g_Q + (((size_t)b * HH + h) * SS + q0) * EE;
    const float* Kg = g_K + ((size_t)b * HH + h) * SS * EE;
    const float* Vg = g_V + ((size_t)b * HH + h) * SS * EE;

    // Q A-fragments in registers, pre-scaled by 1/sqrt(64)
    unsigned qf[2][8][4];
    #pragma unroll
    for (int mt = 0; mt < 2; mt++) {
        int r0 = wm * 32 + mt * 16 + (lane >> 2);
        #pragma unroll
        for (int ks = 0; ks < 8; ks++) {
            int c0 = ks * 8 + (lane & 3);
            qf[mt][ks][0] = f2tf(Qg[(size_t)r0 * EE + c0] * 0.125f);
            qf[mt][ks][1] = f2tf(Qg[(size_t)(r0 + 8) * EE + c0] * 0.125f);
            qf[mt][ks][2] = f2tf(Qg[(size_t)r0 * EE + c0 + 4] * 0.125f);
            qf[mt][ks][3] = f2tf(Qg[(size_t)(r0 + 8) * EE + c0 + 4] * 0.125f);
        }
    }

    float o[2][4][4];
    float mrow[2][2], lrow[2][2];
    #pragma unroll
    for (int mt = 0; mt < 2; mt++) {
        mrow[mt][0] = mrow[mt][1] = -1e30f;
        lrow[mt][0] = lrow[mt][1] = 0.0f;
        #pragma unroll
        for (int j = 0; j < 4; j++)
            #pragma unroll
            for (int v = 0; v < 4; v++) o[mt][j][v] = 0.0f;
    }

    // KV prefetch: thread t owns key row pr = t>>2, 16 e-cols at pc.
    const int pr = t >> 2;
    const int pc = (t & 3) * 16;
    float4 kv[4], vv[4];
    #pragma unroll
    for (int u = 0; u < 4; u++) {
        kv[u] = *(const float4*)(Kg + (size_t)pr * EE + pc + u * 4);
        vv[u] = *(const float4*)(Vg + (size_t)pr * EE + pc + u * 4);
    }

    for (int kt = 0; kt < SS; kt += 64) {
        __syncthreads();   // Kf/Vf/Psm free (prior PV done)

        // Scatter K (B-frag over n=key, k=e) and V (B-frag over n=e, k=key)
        #pragma unroll
        for (int u = 0; u < 4; u++) {
            const float* kp = (const float*)&kv[u];
            const float* vp = (const float*)&vv[u];
            #pragma unroll
            for (int w = 0; w < 4; w++) {
                int e = pc + u * 4 + w;
                Kf[(((e >> 3) * 8 + (pr >> 3)) * 32 + (pr & 7) * 4 + (e & 3)) * 2 + ((e >> 2) & 1)] = f2tf(kp[w]);
                Vf[(((pr >> 3) * 8 + (e >> 3)) * 32 + (e & 7) * 4 + (pr & 3)) * 2 + ((pr >> 2) & 1)] = f2tf(vp[w]);
            }
        }
        __syncthreads();

        if (kt + 64 < SS) {
            #pragma unroll
            for (int u = 0; u < 4; u++) {
                kv[u] = *(const float4*)(Kg + (size_t)(kt + 64 + pr) * EE + pc + u * 4);
                vv[u] = *(const float4*)(Vg + (size_t)(kt + 64 + pr) * EE + pc + u * 4);
            }
        }

        // S = Q K^T (scaled): sc[mt][j][4], warp covers 32q x 32keys
        float sc[2][4][4];
        #pragma unroll
        for (int mt = 0; mt < 2; mt++)
            #pragma unroll
            for (int j = 0; j < 4; j++)
                #pragma unroll
                for (int v = 0; v < 4; v++) sc[mt][j][v] = 0.0f;

        #pragma unroll
        for (int ks = 0; ks < 8; ks++) {
            unsigned bf[4][2];
            #pragma unroll
            for (int j = 0; j < 4; j++) {
                uint2 q = *(const uint2*)&Kf[((ks * 8 + wn * 4 + j) * 32 + lane) * 2];
                bf[j][0] = q.x; bf[j][1] = q.y;
            }
            #pragma unroll
            for (int mt = 0; mt < 2; mt++)
                #pragma unroll
                for (int j = 0; j < 4; j++)
                    mma8(sc[mt][j], qf[mt][ks], bf[j]);
        }

        // Partial row max over this warp's 32 keys (in-lane over j, shuffle over lane&3)
        float pm[2][2];
        #pragma unroll
        for (int mt = 0; mt < 2; mt++) {
            float m0v = fmaxf(sc[mt][0][0], sc[mt][0][1]);
            float m1v = fmaxf(sc[mt][0][2], sc[mt][0][3]);
            #pragma unroll
            for (int j = 1; j < 4; j++) {
                m0v = fmaxf(m0v, fmaxf(sc[mt][j][0], sc[mt][j][1]));
                m1v = fmaxf(m1v, fmaxf(sc[mt][j][2], sc[mt][j][3]));
            }
            m0v = fmaxf(m0v, __shfl_xor_sync(0xffffffffu, m0v, 1));
            m0v = fmaxf(m0v, __shfl_xor_sync(0xffffffffu, m0v, 2));
            m1v = fmaxf(m1v, __shfl_xor_sync(0xffffffffu, m1v, 1));
            m1v = fmaxf(m1v, __shfl_xor_sync(0xffffffffu, m1v, 2));
            pm[mt][0] = m0v; pm[mt][1] = m1v;
        }
        if ((lane & 3) == 0) {
            #pragma unroll
            for (int mt = 0; mt < 2; mt++) {
                int rbase = wm * 32 + mt * 16 + (lane >> 2);
                pmax[wn * 128 + rbase]     = pm[mt][0];
                pmax[wn * 128 + rbase + 8] = pm[mt][1];
            }
        }
        __syncthreads();

        // Combine across the two n-warps; update m, rescale l and O
        float mnew[2][2], corr[2][2];
        #pragma unroll
        for (int mt = 0; mt < 2; mt++) {
            int rbase = wm * 32 + mt * 16 + (lane >> 2);
            #pragma unroll
            for (int hf = 0; hf < 2; hf++) {
                float om = pmax[(wn ^ 1) * 128 + rbase + hf * 8];
                float mn = fmaxf(mrow[mt][hf], fmaxf(pm[mt][hf], om));
                corr[mt][hf] = __expf(mrow[mt][hf] - mn);
                mrow[mt][hf] = mn;
                lrow[mt][hf] *= corr[mt][hf];
                mnew[mt][hf] = mn;
            }
        }
        #pragma unroll
        for (int mt = 0; mt < 2; mt++)
            #pragma unroll
            for (int j = 0; j < 4; j++) {
                o[mt][j][0] *= corr[mt][0];
                o[mt][j][1] *= corr[mt][0];
                o[mt][j][2] *= corr[mt][1];
                o[mt][j][3] *= corr[mt][1];
            }

        // exp, partial sums, write P (tf32 bits) to Psm
        float ps[2][2] = {{0.0f, 0.0f}, {0.0f, 0.0f}};
        #pragma unroll
        for (int mt = 0; mt < 2; mt++) {
            int r = wm * 32 + mt * 16 + (lane >> 2);
            #pragma unroll
            for (int j = 0; j < 4; j++) {
                int c = wn * 32 + j * 8 + 2 * (lane & 3);
                float p0 = __expf(sc[mt][j][0] - mnew[mt][0]);
                float p1 = __expf(sc[mt][j][1] - mnew[mt][0]);
                float p2 = __expf(sc[mt][j][2] - mnew[mt][1]);
                float p3 = __expf(sc[mt][j][3] - mnew[mt][1]);
                ps[mt][0] += p0 + p1;
                ps[mt][1] += p2 + p3;
                *(uint2*)&Psm[r * PLD + c]       = make_uint2(f2tf(p0), f2tf(p1));
                *(uint2*)&Psm[(r + 8) * PLD + c] = make_uint2(f2tf(p2), f2tf(p3));
            }
        }
        #pragma unroll
        for (int mt = 0; mt < 2; mt++)
            #pragma unroll
            for (int hf = 0; hf < 2; hf++) {
                float s = ps[mt][hf];
                s += __shfl_xor_sync(0xffffffffu, s, 1);
                s += __shfl_xor_sync(0xffffffffu, s, 2);
                ps[mt][hf] = s;
            }
        if ((lane & 3) == 0) {
            #pragma unroll
            for (int mt = 0; mt < 2; mt++) {
                int rbase = wm * 32 + mt * 16 + (lane >> 2);
                psum[wn * 128 + rbase]     = ps[mt][0];
                psum[wn * 128 + rbase + 8] = ps[mt][1];
            }
        }
        __syncthreads();

        #pragma unroll
        for (int mt = 0; mt < 2; mt++) {
            int rbase = wm * 32 + mt * 16 + (lane >> 2);
            lrow[mt][0] += ps[mt][0] + psum[(wn ^ 1) * 128 + rbase];
            lrow[mt][1] += ps[mt][1] + psum[(wn ^ 1) * 128 + rbase + 8];
        }

        // O += P V : A = P rows (own 32q x 64keys), B = V frags (e-range wn*32)
        #pragma unroll
        for (int ks = 0; ks < 8; ks++) {
            unsigned pa[2][4];
            #pragma unroll
            for (int mt = 0; mt < 2; mt++) {
                int r = wm * 32 + mt * 16 + (lane >> 2);
                int c = ks * 8 + (lane & 3);
                pa[mt][0] = Psm[r * PLD + c];
                pa[mt][1] = Psm[(r + 8) * PLD + c];
                pa[mt][2] = Psm[r * PLD + c + 4];
                pa[mt][3] = Psm[(r + 8) * PLD + c + 4];
            }
            unsigned vb[4][2];
            #pragma unroll
            for (int j = 0; j < 4; j++) {
                uint2 q = *(const uint2*)&Vf[((ks * 8 + wn * 4 + j) * 32 + lane) * 2];
                vb[j][0] = q.x; vb[j][1] = q.y;
            }
            #pragma unroll
            for (int mt = 0; mt < 2; mt++)
                #pragma unroll
                for (int j = 0; j < 4; j++)
                    mma8(o[mt][j], pa[mt], vb[j]);
        }
    }

    // Epilogue: out[b, q, h*64 + e] = O / l
    #pragma unroll
    for (int mt = 0; mt < 2; mt++) {
        float i0 = 1.0f / lrow[mt][0];
        float i1 = 1.0f / lrow[mt][1];
        int r = q0 + wm * 32 + mt * 16 + (lane >> 2);
        #pragma unroll
        for (int j = 0; j < 4; j++) {
            int e = h * EE + wn * 32 + j * 8 + 2 * (lane & 3);
            *(float2*)&out[((size_t)b * SS + r) * (HH * EE) + e] =
                make_float2(o[mt][j][0] * i0, o[mt][j][1] * i0);
            *(float2*)&out[((size_t)b * SS + r + 8) * (HH * EE) + e] =
                make_float2(o[mt][j][2] * i1, o[mt][j][3] * i1);
        }
    }
}

// ---------------------------------------------------------------------------
// Launch
// ---------------------------------------------------------------------------
extern "C" void kernel_launch(void* const* d_in, const int* in_sizes, int n_in,
                              void* d_out, int out_size)
{
    (void)in_sizes; (void)n_in; (void)out_size;
    const float* x  = (const float*)d_in[0];
    const float* Wq = (const float*)d_in[1];
    const float* Wk = (const float*)d_in[2];
    const float* Wv = (const float*)d_in[3];
    float* out = (float*)d_out;

    cudaFuncSetAttribute(attn_mma,
                         cudaFuncAttributeMaxDynamicSharedMemorySize,
                         ATTN_SMEM_BYTES);

    dim3 gproj(HH * EE / 128, (BB * SS) / 128, 3);   // (8, 64, 3)
    qkv_proj_mma<<<gproj, 256>>>(x, Wq, Wk, Wv);

    dim3 gattn(SS / 128, HH, BB);                     // (16, 16, 4)
    attn_mma<<<gattn, 256, ATTN_SMEM_BYTES>>>(out);
}